// round 3
// baseline (speedup 1.0000x reference)
#include <cuda_runtime.h>

// Fixed problem shapes
#define NN 20000      // nodes
#define EE 640000     // edges
#define HH 128        // hidden
#define FF 64         // input features
#define RR 8          // relations
#define BB 4          // blocks
#define CC 32         // block size
#define DD 3          // edge-attr dims (j)

// -------- device scratch (allocation-free rule) --------
__device__ float    g_h0[NN * HH];                        // x @ feature_emb
__device__ float    g_h1[3 * NN * HH];                    // layer-0 outputs / layer-1 input
__device__ float    g_agg[NN * HH];                       // per-(layer,j) aggregated term
__device__ float    g_sums[(size_t)DD * RR * NN * HH];    // mean-scaled sums [j][r][n][128] (245 MB)
__device__ int      g_deg[NN];
__device__ int      g_start[NN + 1];
__device__ int      g_fill[NN];
__device__ unsigned g_einfo[EE];                          // src | r0<<15 | r1<<18 | r2<<21

// ---- packed f32x2 helpers (Blackwell; ptxas won't auto-fuse) ----
static __device__ __forceinline__ unsigned long long pk2(float lo, float hi) {
    unsigned long long r;
    asm("mov.b64 %0, {%1, %2};" : "=l"(r) : "f"(lo), "f"(hi));
    return r;
}
static __device__ __forceinline__ void upk2(unsigned long long v, float& lo, float& hi) {
    asm("mov.b64 {%0, %1}, %2;" : "=f"(lo), "=f"(hi) : "l"(v));
}
#define FMA2(acc, a, b) \
    asm("fma.rn.f32x2 %0, %1, %2, %0;" : "+l"(acc) : "l"(a), "l"(b))

// ============================================================
// h0 = x @ feature_emb   (N x 64) @ (64 x 128); 2 rows/block
// ============================================================
__global__ __launch_bounds__(256)
void gemm_in_kernel(const float* __restrict__ x, const float* __restrict__ fe) {
    int n = blockIdx.x * 2 + (threadIdx.x >> 7);
    int o = threadIdx.x & 127;
    const float* xr = x + (size_t)n * FF;
    float acc = 0.f;
#pragma unroll
    for (int f = 0; f < FF; f++)
        acc += xr[f] * fe[f * HH + o];
    g_h0[(size_t)n * HH + o] = acc;
}

// ============================================================
// CSR build: zero deg -> histogram -> prefix -> fill (packed einfo)
// ============================================================
__global__ __launch_bounds__(256)
void k_zero_deg() {
    int i = blockIdx.x * 256 + threadIdx.x;
    if (i < NN) g_deg[i] = 0;
}

__global__ __launch_bounds__(256)
void k_count(const int* __restrict__ dst) {
    int e = blockIdx.x * 256 + threadIdx.x;
    if (e < EE) atomicAdd(&g_deg[dst[e]], 1);
}

// single block, 1024 threads; chunk of 20 per thread (covers 20480 >= NN)
__global__ __launch_bounds__(1024)
void k_prefix() {
    __shared__ int partial[1024];
    int t = threadIdx.x;
    const int CH = 20;
    int base = t * CH;
    int local[CH];
    int s = 0;
#pragma unroll
    for (int k = 0; k < CH; k++) {
        int i = base + k;
        int v = (i < NN) ? g_deg[i] : 0;
        local[k] = s;      // exclusive within chunk
        s += v;
    }
    partial[t] = s;
    __syncthreads();
    for (int off = 1; off < 1024; off <<= 1) {
        int v = (t >= off) ? partial[t - off] : 0;
        __syncthreads();
        partial[t] += v;
        __syncthreads();
    }
    int prev = t ? partial[t - 1] : 0;
#pragma unroll
    for (int k = 0; k < CH; k++) {
        int i = base + k;
        if (i < NN) {
            int st = prev + local[k];
            g_start[i] = st;
            g_fill[i]  = st;
        }
    }
    if (t == 1023) g_start[NN] = partial[1023];
}

__global__ __launch_bounds__(256)
void k_fill(const int* __restrict__ src, const int* __restrict__ dst,
            const int* __restrict__ ea) {
    int e = blockIdx.x * 256 + threadIdx.x;
    if (e >= EE) return;
    int d = dst[e];
    int pos = atomicAdd(&g_fill[d], 1);
    unsigned info = (unsigned)src[e]
                  | ((unsigned)ea[(size_t)e * 3 + 0] << 15)
                  | ((unsigned)ea[(size_t)e * 3 + 1] << 18)
                  | ((unsigned)ea[(size_t)e * 3 + 2] << 21);
    g_einfo[pos] = info;
}

// ============================================================
// FUSED aggregation: one warp per dst, ONE gather of h[src] per edge
// per layer; 24 mean buckets (3 j x 8 r) in smem; plain stores.
// Writes g_sums[j][r][d][:], mean-scaled. No atomics, no zero-pass.
// Block = 64 threads (2 warps, 2 dsts), 24 KB smem -> 9 blocks/SM.
// ============================================================
__global__ __launch_bounds__(64)
void k_agg(int layer) {
    __shared__ float buck[2][DD * RR][HH];   // 24 KB
    __shared__ int   scnt[2][DD * RR];

    int t = threadIdx.x, w = t >> 5, lane = t & 31;
    int d = blockIdx.x * 2 + w;
    const float* h = layer ? g_h1 : g_h0;

    // zero this warp's buckets & counts (24*128 = 3072 floats = 768 float4)
    float4* bp = (float4*)&buck[w][0][0];
#pragma unroll
    for (int q = 0; q < 24; q++) bp[lane + q * 32] = make_float4(0.f, 0.f, 0.f, 0.f);
    if (lane < DD * RR) scnt[w][lane] = 0;
    __syncwarp();

    int s0 = g_start[d], s1 = g_start[d + 1];

    unsigned info = 0;
    float4 v = make_float4(0.f, 0.f, 0.f, 0.f);
    if (s0 < s1) {
        info = g_einfo[s0];
        v = *(const float4*)(h + (size_t)(info & 0x7FFF) * HH + lane * 4);
    }
    for (int idx = s0; idx < s1; idx++) {
        unsigned ninfo = 0;
        float4 nv = make_float4(0.f, 0.f, 0.f, 0.f);
        if (idx + 1 < s1) {                      // prefetch next edge
            ninfo = g_einfo[idx + 1];
            nv = *(const float4*)(h + (size_t)(ninfo & 0x7FFF) * HH + lane * 4);
        }
        int r0 = (info >> 15) & 7;
        int r1 = (info >> 18) & 7;
        int r2 = (info >> 21) & 7;
        if (lane == 0) {
            scnt[w][r0]++;
            scnt[w][RR + r1]++;
            scnt[w][2 * RR + r2]++;
        }
        float4* b0 = (float4*)&buck[w][r0][lane * 4];
        float4 t0 = *b0;
        t0.x += v.x; t0.y += v.y; t0.z += v.z; t0.w += v.w;
        *b0 = t0;
        float4* b1 = (float4*)&buck[w][RR + r1][lane * 4];
        float4 t1 = *b1;
        t1.x += v.x; t1.y += v.y; t1.z += v.z; t1.w += v.w;
        *b1 = t1;
        float4* b2 = (float4*)&buck[w][2 * RR + r2][lane * 4];
        float4 t2 = *b2;
        t2.x += v.x; t2.y += v.y; t2.z += v.z; t2.w += v.w;
        *b2 = t2;
        info = ninfo;
        v = nv;
    }
    __syncwarp();

#pragma unroll
    for (int jr = 0; jr < DD * RR; jr++) {
        float sc = 1.f / fmaxf((float)scnt[w][jr], 1.f);
        float4 bv = *(float4*)&buck[w][jr][lane * 4];
        bv.x *= sc; bv.y *= sc; bv.z *= sc; bv.w *= sc;
        *(float4*)(g_sums + ((size_t)jr * NN + d) * HH + lane * 4) = bv;
    }
}

// ============================================================
// transform: agg[n, b*32+d] = sum_r sum_c meanS[j][r][n][b*32+c] * W[r,b,c,d]
// 32 nodes/block, 256 threads; f32x2 packed FMA inner product.
// ============================================================
__global__ __launch_bounds__(256)
void k_transform(const float* __restrict__ W, int j) {
    __shared__ float S[32][HH];     // 16 KB

    int t = threadIdx.x;
    int nodeBase = blockIdx.x * 32;
    int o = t & 127;
    int grp = t >> 7;               // 0 / 1 (16 nodes each)
    int b = o >> 5, d = o & 31;
    const float* Sbase = g_sums + (size_t)j * RR * NN * HH;

    unsigned long long acc2[16];
#pragma unroll
    for (int q = 0; q < 16; q++) acc2[q] = 0ull;

    for (int r = 0; r < RR; r++) {
        __syncthreads();
#pragma unroll
        for (int q = 0; q < 16; q++) {
            int lin = t + q * 256;              // 0..4095
            int nl = lin >> 7, col = lin & 127;
            S[nl][col] = Sbase[((size_t)(r * NN + nodeBase + nl)) * HH + col];
        }
        __syncthreads();

        unsigned long long wp[16];
#pragma unroll
        for (int c2 = 0; c2 < 16; c2++) {
            const float* wq = W + ((size_t)((r * BB + b) * CC + 2 * c2)) * CC + d;
            wp[c2] = pk2(__ldg(wq), __ldg(wq + CC));
        }

#pragma unroll
        for (int q = 0; q < 16; q++) {
            int nl = grp * 16 + q;
            const float4* Srow = (const float4*)&S[nl][b * CC];
#pragma unroll
            for (int c4 = 0; c4 < 8; c4++) {
                float4 sv = Srow[c4];
                FMA2(acc2[q], pk2(sv.x, sv.y), wp[2 * c4 + 0]);
                FMA2(acc2[q], pk2(sv.z, sv.w), wp[2 * c4 + 1]);
            }
        }
    }

#pragma unroll
    for (int q = 0; q < 16; q++) {
        int nl = grp * 16 + q;
        float lo, hi;
        upk2(acc2[q], lo, hi);
        g_agg[((size_t)(nodeBase + nl)) * HH + o] = lo + hi;
    }
}

// ============================================================
// out[row,:] = relu( (row<N ? agg : 0) + h[row,:] @ root + bias )
// BM=64, BN=128, K-chunk=32, 512 threads, 4x4 micro-tile, f32x2 FMA.
// ============================================================
__global__ __launch_bounds__(512)
void root_fused_kernel(const float* __restrict__ root, const float* __restrict__ bias,
                       int Np, float* __restrict__ extOut, size_t off, int layer) {
    __shared__ float hT[32][64];    // [k][row]
    __shared__ float rS[32][128];   // [k][col]

    const float* hin = layer ? g_h1 : g_h0;
    float* outp = extOut ? extOut : (g_h1 + off);

    int tx = threadIdx.x;
    int row0 = blockIdx.x * 64;
    int r4 = (tx & 15) * 4;
    int c4 = (tx >> 4) * 4;

    unsigned long long acc2[4][2];
#pragma unroll
    for (int i = 0; i < 4; i++) { acc2[i][0] = 0ull; acc2[i][1] = 0ull; }

    for (int k0 = 0; k0 < HH; k0 += 32) {
        __syncthreads();
        {   // hT: 64 rows x 32 k (transposed store), one float4 per thread
            int row = tx >> 3;
            int kq = (tx & 7) * 4;
            float4 hv = make_float4(0.f, 0.f, 0.f, 0.f);
            int grow = row0 + row;
            if (grow < Np)
                hv = *(const float4*)(hin + (size_t)grow * HH + k0 + kq);
            hT[kq + 0][row] = hv.x;
            hT[kq + 1][row] = hv.y;
            hT[kq + 2][row] = hv.z;
            hT[kq + 3][row] = hv.w;
        }
#pragma unroll
        for (int q = 0; q < 2; q++) {   // rS: 32 k x 128 cols
            int lin = tx + q * 512;
            int k = lin >> 5;
            int cq = (lin & 31) * 4;
            *(float4*)&rS[k][cq] = *(const float4*)(root + (size_t)(k0 + k) * HH + cq);
        }
        __syncthreads();

#pragma unroll
        for (int k = 0; k < 32; k++) {
            float4 a = *(const float4*)&hT[k][r4];
            float4 bb = *(const float4*)&rS[k][c4];
            unsigned long long bp0 = pk2(bb.x, bb.y);
            unsigned long long bp1 = pk2(bb.z, bb.w);
            float av[4] = {a.x, a.y, a.z, a.w};
#pragma unroll
            for (int i = 0; i < 4; i++) {
                unsigned long long ai = pk2(av[i], av[i]);
                FMA2(acc2[i][0], ai, bp0);
                FMA2(acc2[i][1], ai, bp1);
            }
        }
    }

    float bv0 = bias[c4 + 0], bv1 = bias[c4 + 1], bv2 = bias[c4 + 2], bv3 = bias[c4 + 3];
#pragma unroll
    for (int i = 0; i < 4; i++) {
        int row = row0 + r4 + i;
        if (row >= Np) break;
        float4 o4;
        upk2(acc2[i][0], o4.x, o4.y);
        upk2(acc2[i][1], o4.z, o4.w);
        o4.x += bv0; o4.y += bv1; o4.z += bv2; o4.w += bv3;
        if (row < NN) {
            const float4 ag = *(const float4*)(g_agg + (size_t)row * HH + c4);
            o4.x += ag.x; o4.y += ag.y; o4.z += ag.z; o4.w += ag.w;
        }
        o4.x = fmaxf(o4.x, 0.f);
        o4.y = fmaxf(o4.y, 0.f);
        o4.z = fmaxf(o4.z, 0.f);
        o4.w = fmaxf(o4.w, 0.f);
        *(float4*)(outp + (size_t)row * HH + c4) = o4;
    }
}

// ============================================================
extern "C" void kernel_launch(void* const* d_in, const int* in_sizes, int n_in,
                              void* d_out, int out_size) {
    const float* x  = (const float*)d_in[0];
    const int*   ei = (const int*)  d_in[1];
    const int*   ea = (const int*)  d_in[2];
    const float* fe = (const float*)d_in[3];
    const float* cw = (const float*)d_in[4];
    const float* cr = (const float*)d_in[5];
    const float* cb = (const float*)d_in[6];
    float* out = (float*)d_out;

    const int* src = ei;
    const int* dst = ei + EE;

    gemm_in_kernel<<<NN / 2, 256>>>(x, fe);

    // CSR build (once per launch; replay-safe: every buffer rewritten each call)
    k_zero_deg<<<(NN + 255) / 256, 256>>>();
    k_count<<<(EE + 255) / 256, 256>>>(dst);
    k_prefix<<<1, 1024>>>();
    k_fill<<<(EE + 255) / 256, 256>>>(src, dst, ea);

    for (int layer = 0; layer < 2; layer++) {
        int Np = (layer == 0) ? NN : 3 * NN;

        // one fused gather+bucket pass per layer (covers all 3 j's)
        k_agg<<<NN / 2, 64>>>(layer);

        for (int j = 0; j < 3; j++) {
            const float* W = cw + (size_t)(layer * 3 + j) * RR * BB * CC * CC;
            k_transform<<<NN / 32, 256>>>(W, j);

            const float* root = cr + (size_t)(layer * 3 + j) * HH * HH;
            const float* bias = cb + (size_t)(layer * 3 + j) * HH;
            float* extOut = (layer == 0) ? nullptr : (out + (size_t)j * Np * HH);
            size_t off = (size_t)j * (size_t)Np * HH;
            root_fused_kernel<<<(Np + 63) / 64, 512>>>(root, bias, Np, extOut, off, layer);
        }
    }
}

// round 11
// speedup vs baseline: 1.1284x; 1.1284x over previous
#include <cuda_runtime.h>

// Fixed problem shapes
#define NN 20000      // nodes
#define EE 640000     // edges
#define HH 128        // hidden
#define FF 64         // input features
#define RR 8          // relations
#define BB 4          // blocks
#define CC 32         // block size
#define DD 3          // edge-attr dims (j)
#define JR 24         // DD*RR

// -------- device scratch (allocation-free rule) --------
__device__ float    g_h0[NN * HH];                        // x @ feature_emb
__device__ float    g_h1[3 * NN * HH];                    // layer-0 outputs / layer-1 input
__device__ float    g_agg[DD * NN * HH];                  // per-layer aggregated terms, all 3 j
__device__ float    g_sums[(size_t)JR * NN * HH];         // mean-scaled sums [jr][n][128] (245 MB)
__device__ int      g_deg[NN];
__device__ int      g_start[NN + 1];
__device__ int      g_fill[NN];
__device__ unsigned g_einfo[EE];                          // src | r0<<15 | r1<<18 | r2<<21

// ---- packed f32x2 helpers (Blackwell; ptxas won't auto-fuse) ----
static __device__ __forceinline__ unsigned long long pk2(float lo, float hi) {
    unsigned long long r;
    asm("mov.b64 %0, {%1, %2};" : "=l"(r) : "f"(lo), "f"(hi));
    return r;
}
static __device__ __forceinline__ void upk2(unsigned long long v, float& lo, float& hi) {
    asm("mov.b64 {%0, %1}, %2;" : "=f"(lo), "=f"(hi) : "l"(v));
}
#define FMA2(acc, a, b) \
    asm("fma.rn.f32x2 %0, %1, %2, %0;" : "+l"(acc) : "l"(a), "l"(b))

// ============================================================
// h0 = x @ feature_emb   (N x 64) @ (64 x 128); 2 rows/block
// also zeroes g_deg for the CSR build
// ============================================================
__global__ __launch_bounds__(256)
void gemm_in_kernel(const float* __restrict__ x, const float* __restrict__ fe) {
    int gt = blockIdx.x * 256 + threadIdx.x;
    if (gt < NN) g_deg[gt] = 0;

    int n = blockIdx.x * 2 + (threadIdx.x >> 7);
    int o = threadIdx.x & 127;
    const float* xr = x + (size_t)n * FF;
    float acc = 0.f;
#pragma unroll
    for (int f = 0; f < FF; f++)
        acc += xr[f] * fe[f * HH + o];
    g_h0[(size_t)n * HH + o] = acc;
}

// ============================================================
// CSR build (histogram -> prefix -> fill); proven round-2 code
// ============================================================
__global__ __launch_bounds__(256)
void k_count(const int* __restrict__ dst) {
    int e = blockIdx.x * 256 + threadIdx.x;
    if (e < EE) atomicAdd(&g_deg[dst[e]], 1);
}

// single block, 1024 threads; chunk of 20 per thread (covers 20480 >= NN)
__global__ __launch_bounds__(1024)
void k_prefix() {
    __shared__ int partial[1024];
    int t = threadIdx.x;
    const int CH = 20;
    int base = t * CH;
    int local[CH];
    int s = 0;
#pragma unroll
    for (int k = 0; k < CH; k++) {
        int i = base + k;
        int v = (i < NN) ? g_deg[i] : 0;
        local[k] = s;      // exclusive within chunk
        s += v;
    }
    partial[t] = s;
    __syncthreads();
    for (int off = 1; off < 1024; off <<= 1) {
        int v = (t >= off) ? partial[t - off] : 0;
        __syncthreads();
        partial[t] += v;
        __syncthreads();
    }
    int prev = t ? partial[t - 1] : 0;
#pragma unroll
    for (int k = 0; k < CH; k++) {
        int i = base + k;
        if (i < NN) {
            int st = prev + local[k];
            g_start[i] = st;
            g_fill[i]  = st;
        }
    }
    if (t == 1023) g_start[NN] = partial[1023];
}

__global__ __launch_bounds__(256)
void k_fill(const int* __restrict__ src, const int* __restrict__ dst,
            const int* __restrict__ ea) {
    int e = blockIdx.x * 256 + threadIdx.x;
    if (e >= EE) return;
    int d = dst[e];
    int pos = atomicAdd(&g_fill[d], 1);
    unsigned info = (unsigned)src[e]
                  | ((unsigned)ea[(size_t)e * 3 + 0] << 15)
                  | ((unsigned)ea[(size_t)e * 3 + 1] << 18)
                  | ((unsigned)ea[(size_t)e * 3 + 2] << 21);
    g_einfo[pos] = info;
}

// ============================================================
// FUSED aggregation (proven round-2 code): one warp per dst, one
// gather of h[src] per edge per layer; 24 mean buckets in smem.
// ============================================================
__global__ __launch_bounds__(64)
void k_agg(int layer) {
    __shared__ float buck[2][JR][HH];   // 24 KB
    __shared__ int   scnt[2][JR];

    int t = threadIdx.x, w = t >> 5, lane = t & 31;
    int d = blockIdx.x * 2 + w;
    const float* h = layer ? g_h1 : g_h0;

    float4* bp = (float4*)&buck[w][0][0];
#pragma unroll
    for (int q = 0; q < JR; q++) bp[lane + q * 32] = make_float4(0.f, 0.f, 0.f, 0.f);
    if (lane < JR) scnt[w][lane] = 0;
    __syncwarp();

    int s0 = g_start[d], s1 = g_start[d + 1];

    unsigned info = 0;
    float4 v = make_float4(0.f, 0.f, 0.f, 0.f);
    if (s0 < s1) {
        info = g_einfo[s0];
        v = *(const float4*)(h + (size_t)(info & 0x7FFF) * HH + lane * 4);
    }
    for (int idx = s0; idx < s1; idx++) {
        unsigned ninfo = 0;
        float4 nv = make_float4(0.f, 0.f, 0.f, 0.f);
        if (idx + 1 < s1) {                      // prefetch next edge
            ninfo = g_einfo[idx + 1];
            nv = *(const float4*)(h + (size_t)(ninfo & 0x7FFF) * HH + lane * 4);
        }
        int r0 = (info >> 15) & 7;
        int r1 = (info >> 18) & 7;
        int r2 = (info >> 21) & 7;
        if (lane == 0) {
            scnt[w][r0]++;
            scnt[w][RR + r1]++;
            scnt[w][2 * RR + r2]++;
        }
        float4* b0 = (float4*)&buck[w][r0][lane * 4];
        float4 t0 = *b0;
        t0.x += v.x; t0.y += v.y; t0.z += v.z; t0.w += v.w;
        *b0 = t0;
        float4* b1 = (float4*)&buck[w][RR + r1][lane * 4];
        float4 t1 = *b1;
        t1.x += v.x; t1.y += v.y; t1.z += v.z; t1.w += v.w;
        *b1 = t1;
        float4* b2 = (float4*)&buck[w][2 * RR + r2][lane * 4];
        float4 t2 = *b2;
        t2.x += v.x; t2.y += v.y; t2.z += v.z; t2.w += v.w;
        *b2 = t2;
        info = ninfo;
        v = nv;
    }
    __syncwarp();

#pragma unroll
    for (int jr = 0; jr < JR; jr++) {
        float sc = 1.f / fmaxf((float)scnt[w][jr], 1.f);
        float4 bv = *(float4*)&buck[w][jr][lane * 4];
        bv.x *= sc; bv.y *= sc; bv.z *= sc; bv.w *= sc;
        *(float4*)(g_sums + ((size_t)jr * NN + d) * HH + lane * 4) = bv;
    }
}

// ============================================================
// transform (ALL 3 j in one launch, blockIdx.y = j):
// agg[j][n, b*32+d] = sum_r sum_c meanS[j][r][n][c] * W[layer,j][r,b,c,d]
// 32 nodes/block, 256 threads; b64 smem reads feed fma.rn.f32x2.
// ============================================================
__global__ __launch_bounds__(256)
void k_transform(const float* __restrict__ Wl) {
    __shared__ float S[32][HH];     // 16 KB

    int j = blockIdx.y;
    const float* W = Wl + (size_t)j * RR * BB * CC * CC;
    const float* Sbase = g_sums + (size_t)j * RR * NN * HH;
    int t = threadIdx.x;
    int nodeBase = blockIdx.x * 32;
    int o = t & 127;
    int grp = t >> 7;               // 0 / 1 (16 nodes each)
    int b = o >> 5, d = o & 31;

    unsigned long long acc2[16];
#pragma unroll
    for (int q = 0; q < 16; q++) acc2[q] = 0ull;

    for (int r = 0; r < RR; r++) {
        __syncthreads();
#pragma unroll
        for (int q = 0; q < 16; q++) {
            int lin = t + q * 256;              // 0..4095
            int nl = lin >> 7, col = lin & 127;
            S[nl][col] = Sbase[((size_t)(r * NN + nodeBase + nl)) * HH + col];
        }
        __syncthreads();

        unsigned long long wp[16];
#pragma unroll
        for (int c2 = 0; c2 < 16; c2++) {
            const float* wq = W + ((size_t)((r * BB + b) * CC + 2 * c2)) * CC + d;
            wp[c2] = pk2(__ldg(wq), __ldg(wq + CC));
        }

#pragma unroll
        for (int q = 0; q < 16; q++) {
            int nl = grp * 16 + q;
            const unsigned long long* Srow = (const unsigned long long*)&S[nl][b * CC];
#pragma unroll
            for (int c2 = 0; c2 < 16; c2++)
                FMA2(acc2[q], Srow[c2], wp[c2]);
        }
    }

    float* aggj = g_agg + (size_t)j * NN * HH;
#pragma unroll
    for (int q = 0; q < 16; q++) {
        int nl = grp * 16 + q;
        float lo, hi;
        upk2(acc2[q], lo, hi);
        aggj[((size_t)(nodeBase + nl)) * HH + o] = lo + hi;
    }
}

// ============================================================
// root (ALL 3 j in one launch, blockIdx.y = j):
// out[j][row,:] = relu( (row<N ? agg[j] : 0) + h[row,:] @ root[j] + bias[j] )
// IMPORTANT: g_h1 is resolved in DEVICE code (extOut==nullptr selector);
// referencing a __device__ global in host code passes a garbage pointer.
// ============================================================
__global__ __launch_bounds__(512)
void root_fused_kernel(const float* __restrict__ rootL, const float* __restrict__ biasL,
                       int Np, float* __restrict__ extOut, int layer) {
    __shared__ float hT[32][64];    // [k][row]
    __shared__ float rS[32][128];   // [k][col]

    int j = blockIdx.y;
    const float* root = rootL + (size_t)j * HH * HH;
    const float* bias = biasL + (size_t)j * HH;
    const float* hin = layer ? g_h1 : g_h0;
    float* outp = (extOut ? extOut : g_h1) + (size_t)j * (size_t)Np * HH;
    const float* aggj = g_agg + (size_t)j * NN * HH;

    int tx = threadIdx.x;
    int row0 = blockIdx.x * 64;
    int r4 = (tx & 15) * 4;
    int c4 = (tx >> 4) * 4;

    unsigned long long acc2[4][2];
#pragma unroll
    for (int i = 0; i < 4; i++) { acc2[i][0] = 0ull; acc2[i][1] = 0ull; }

    for (int k0 = 0; k0 < HH; k0 += 32) {
        __syncthreads();
        {   // hT: 64 rows x 32 k (transposed store), one float4 per thread
            int row = tx >> 3;
            int kq = (tx & 7) * 4;
            float4 hv = make_float4(0.f, 0.f, 0.f, 0.f);
            int grow = row0 + row;
            if (grow < Np)
                hv = *(const float4*)(hin + (size_t)grow * HH + k0 + kq);
            hT[kq + 0][row] = hv.x;
            hT[kq + 1][row] = hv.y;
            hT[kq + 2][row] = hv.z;
            hT[kq + 3][row] = hv.w;
        }
#pragma unroll
        for (int q = 0; q < 2; q++) {   // rS: 32 k x 128 cols
            int lin = tx + q * 512;
            int k = lin >> 5;
            int cq = (lin & 31) * 4;
            *(float4*)&rS[k][cq] = *(const float4*)(root + (size_t)(k0 + k) * HH + cq);
        }
        __syncthreads();

#pragma unroll
        for (int k = 0; k < 32; k++) {
            float4 a = *(const float4*)&hT[k][r4];
            const unsigned long long* bpp = (const unsigned long long*)&rS[k][c4];
            unsigned long long bp0 = bpp[0];
            unsigned long long bp1 = bpp[1];
            float av[4] = {a.x, a.y, a.z, a.w};
#pragma unroll
            for (int i = 0; i < 4; i++) {
                unsigned long long ai = pk2(av[i], av[i]);
                FMA2(acc2[i][0], ai, bp0);
                FMA2(acc2[i][1], ai, bp1);
            }
        }
    }

    float bv0 = bias[c4 + 0], bv1 = bias[c4 + 1], bv2 = bias[c4 + 2], bv3 = bias[c4 + 3];
#pragma unroll
    for (int i = 0; i < 4; i++) {
        int row = row0 + r4 + i;
        if (row >= Np) break;
        float4 o4;
        upk2(acc2[i][0], o4.x, o4.y);
        upk2(acc2[i][1], o4.z, o4.w);
        o4.x += bv0; o4.y += bv1; o4.z += bv2; o4.w += bv3;
        if (row < NN) {
            const float4 ag = *(const float4*)(aggj + (size_t)row * HH + c4);
            o4.x += ag.x; o4.y += ag.y; o4.z += ag.z; o4.w += ag.w;
        }
        o4.x = fmaxf(o4.x, 0.f);
        o4.y = fmaxf(o4.y, 0.f);
        o4.z = fmaxf(o4.z, 0.f);
        o4.w = fmaxf(o4.w, 0.f);
        *(float4*)(outp + (size_t)row * HH + c4) = o4;
    }
}

// ============================================================
extern "C" void kernel_launch(void* const* d_in, const int* in_sizes, int n_in,
                              void* d_out, int out_size) {
    const float* x  = (const float*)d_in[0];
    const int*   ei = (const int*)  d_in[1];
    const int*   ea = (const int*)  d_in[2];
    const float* fe = (const float*)d_in[3];
    const float* cw = (const float*)d_in[4];
    const float* cr = (const float*)d_in[5];
    const float* cb = (const float*)d_in[6];
    float* out = (float*)d_out;

    const int* src = ei;
    const int* dst = ei + EE;

    gemm_in_kernel<<<NN / 2, 256>>>(x, fe);     // also zeroes g_deg
    k_count<<<(EE + 255) / 256, 256>>>(dst);
    k_prefix<<<1, 1024>>>();
    k_fill<<<(EE + 255) / 256, 256>>>(src, dst, ea);

    for (int layer = 0; layer < 2; layer++) {
        int Np = (layer == 0) ? NN : 3 * NN;

        k_agg<<<NN / 2, 64>>>(layer);           // fused gather+bucket for all 3 j

        const float* Wl    = cw + (size_t)layer * 3 * RR * BB * CC * CC;
        const float* rootL = cr + (size_t)layer * 3 * HH * HH;
        const float* biasL = cb + (size_t)layer * 3 * HH;

        dim3 gT(NN / 32, 3);
        k_transform<<<gT, 256>>>(Wl);           // all 3 j in one launch

        // layer 0 -> device-resolved g_h1 (extOut = nullptr); layer 1 -> d_out
        float* extOut = (layer == 0) ? nullptr : out;
        dim3 gR((Np + 63) / 64, 3);
        root_fused_kernel<<<gR, 512>>>(rootL, biasL, Np, extOut, layer);
    }
}

// round 12
// speedup vs baseline: 1.1813x; 1.0468x over previous
#include <cuda_runtime.h>
#include <cuda_fp16.h>

// Fixed problem shapes
#define NN 20000      // nodes
#define EE 640000     // edges
#define HH 128        // hidden
#define FF 64         // input features
#define RR 8          // relations
#define BB 4          // blocks
#define CC 32         // block size
#define DD 3          // edge-attr dims (j)
#define JR 24         // DD*RR

// -------- device scratch (allocation-free rule) --------
__device__ float    g_h0[NN * HH];                        // x @ feature_emb
__device__ float    g_h1[3 * NN * HH];                    // layer-0 outputs / layer-1 input
__device__ float    g_agg[DD * NN * HH];                  // per-layer aggregated terms, all 3 j
__device__ __half2  g_sums_h[(size_t)JR * NN * 64];       // mean sums [jr][n][64 half2] (123 MB ~ L2-resident)
__device__ int      g_deg[NN];
__device__ int      g_start[NN + 1];
__device__ int      g_fill[NN];
__device__ unsigned g_einfo[EE];                          // src | r0<<15 | r1<<18 | r2<<21

// ---- packed f32x2 helpers (Blackwell; ptxas won't auto-fuse) ----
static __device__ __forceinline__ unsigned long long pk2(float lo, float hi) {
    unsigned long long r;
    asm("mov.b64 %0, {%1, %2};" : "=l"(r) : "f"(lo), "f"(hi));
    return r;
}
static __device__ __forceinline__ void upk2(unsigned long long v, float& lo, float& hi) {
    asm("mov.b64 {%0, %1}, %2;" : "=f"(lo), "=f"(hi) : "l"(v));
}
#define FMA2(acc, a, b) \
    asm("fma.rn.f32x2 %0, %1, %2, %0;" : "+l"(acc) : "l"(a), "l"(b))

// ============================================================
// h0 = x @ feature_emb   (N x 64) @ (64 x 128); 2 rows/block
// also zeroes g_deg for the CSR build
// ============================================================
__global__ __launch_bounds__(256)
void gemm_in_kernel(const float* __restrict__ x, const float* __restrict__ fe) {
    int gt = blockIdx.x * 256 + threadIdx.x;
    if (gt < NN) g_deg[gt] = 0;

    int n = blockIdx.x * 2 + (threadIdx.x >> 7);
    int o = threadIdx.x & 127;
    const float* xr = x + (size_t)n * FF;
    float acc = 0.f;
#pragma unroll
    for (int f = 0; f < FF; f++)
        acc += xr[f] * fe[f * HH + o];
    g_h0[(size_t)n * HH + o] = acc;
}

// ============================================================
// CSR build (histogram -> prefix -> fill); proven code
// ============================================================
__global__ __launch_bounds__(256)
void k_count(const int* __restrict__ dst) {
    int e = blockIdx.x * 256 + threadIdx.x;
    if (e < EE) atomicAdd(&g_deg[dst[e]], 1);
}

// single block, 1024 threads; chunk of 20 per thread (covers 20480 >= NN)
__global__ __launch_bounds__(1024)
void k_prefix() {
    __shared__ int partial[1024];
    int t = threadIdx.x;
    const int CH = 20;
    int base = t * CH;
    int local[CH];
    int s = 0;
#pragma unroll
    for (int k = 0; k < CH; k++) {
        int i = base + k;
        int v = (i < NN) ? g_deg[i] : 0;
        local[k] = s;      // exclusive within chunk
        s += v;
    }
    partial[t] = s;
    __syncthreads();
    for (int off = 1; off < 1024; off <<= 1) {
        int v = (t >= off) ? partial[t - off] : 0;
        __syncthreads();
        partial[t] += v;
        __syncthreads();
    }
    int prev = t ? partial[t - 1] : 0;
#pragma unroll
    for (int k = 0; k < CH; k++) {
        int i = base + k;
        if (i < NN) {
            int st = prev + local[k];
            g_start[i] = st;
            g_fill[i]  = st;
        }
    }
    if (t == 1023) g_start[NN] = partial[1023];
}

__global__ __launch_bounds__(256)
void k_fill(const int* __restrict__ src, const int* __restrict__ dst,
            const int* __restrict__ ea) {
    int e = blockIdx.x * 256 + threadIdx.x;
    if (e >= EE) return;
    int d = dst[e];
    int pos = atomicAdd(&g_fill[d], 1);
    unsigned info = (unsigned)src[e]
                  | ((unsigned)ea[(size_t)e * 3 + 0] << 15)
                  | ((unsigned)ea[(size_t)e * 3 + 1] << 18)
                  | ((unsigned)ea[(size_t)e * 3 + 2] << 21);
    g_einfo[pos] = info;
}

// ============================================================
// FUSED aggregation: one warp per dst, one gather of h[src] per
// edge per layer; 24 mean buckets in smem (fp32 accumulation).
// ONLY CHANGE vs 909us version: epilogue converts to fp16 g_sums_h.
// ============================================================
__global__ __launch_bounds__(64)
void k_agg(int layer) {
    __shared__ float buck[2][JR][HH];   // 24 KB
    __shared__ int   scnt[2][JR];

    int t = threadIdx.x, w = t >> 5, lane = t & 31;
    int d = blockIdx.x * 2 + w;
    const float* h = layer ? g_h1 : g_h0;

    float4* bp = (float4*)&buck[w][0][0];
#pragma unroll
    for (int q = 0; q < JR; q++) bp[lane + q * 32] = make_float4(0.f, 0.f, 0.f, 0.f);
    if (lane < JR) scnt[w][lane] = 0;
    __syncwarp();

    int s0 = g_start[d], s1 = g_start[d + 1];

    unsigned info = 0;
    float4 v = make_float4(0.f, 0.f, 0.f, 0.f);
    if (s0 < s1) {
        info = g_einfo[s0];
        v = *(const float4*)(h + (size_t)(info & 0x7FFF) * HH + lane * 4);
    }
    for (int idx = s0; idx < s1; idx++) {
        unsigned ninfo = 0;
        float4 nv = make_float4(0.f, 0.f, 0.f, 0.f);
        if (idx + 1 < s1) {                      // prefetch next edge
            ninfo = g_einfo[idx + 1];
            nv = *(const float4*)(h + (size_t)(ninfo & 0x7FFF) * HH + lane * 4);
        }
        int r0 = (info >> 15) & 7;
        int r1 = (info >> 18) & 7;
        int r2 = (info >> 21) & 7;
        if (lane == 0) {
            scnt[w][r0]++;
            scnt[w][RR + r1]++;
            scnt[w][2 * RR + r2]++;
        }
        float4* b0 = (float4*)&buck[w][r0][lane * 4];
        float4 t0 = *b0;
        t0.x += v.x; t0.y += v.y; t0.z += v.z; t0.w += v.w;
        *b0 = t0;
        float4* b1 = (float4*)&buck[w][RR + r1][lane * 4];
        float4 t1 = *b1;
        t1.x += v.x; t1.y += v.y; t1.z += v.z; t1.w += v.w;
        *b1 = t1;
        float4* b2 = (float4*)&buck[w][2 * RR + r2][lane * 4];
        float4 t2 = *b2;
        t2.x += v.x; t2.y += v.y; t2.z += v.z; t2.w += v.w;
        *b2 = t2;
        info = ninfo;
        v = nv;
    }
    __syncwarp();

    // epilogue: mean-scale, convert to fp16, store (uint2 = 2x half2 per lane)
#pragma unroll
    for (int jr = 0; jr < JR; jr++) {
        float sc = 1.f / fmaxf((float)scnt[w][jr], 1.f);
        float4 bv = *(float4*)&buck[w][jr][lane * 4];
        bv.x *= sc; bv.y *= sc; bv.z *= sc; bv.w *= sc;
        __half2 ha = __floats2half2_rn(bv.x, bv.y);
        __half2 hb = __floats2half2_rn(bv.z, bv.w);
        unsigned ua = *(unsigned*)&ha;
        unsigned ub = *(unsigned*)&hb;
        *(uint2*)(g_sums_h + ((size_t)jr * NN + d) * 64 + lane * 2) = make_uint2(ua, ub);
    }
}

// ============================================================
// transform (ALL 3 j in one launch, blockIdx.y = j):
// agg[j][n, b*32+d] = sum_r sum_c meanS[j][r][n][c] * W[layer,j][r,b,c,d]
// ONLY CHANGE vs 909us version: staging reads fp16 and converts to fp32 smem.
// ============================================================
__global__ __launch_bounds__(256)
void k_transform(const float* __restrict__ Wl) {
    __shared__ float S[32][HH];     // 16 KB

    int j = blockIdx.y;
    const float* W = Wl + (size_t)j * RR * BB * CC * CC;
    const __half2* Sb = g_sums_h + (size_t)j * RR * NN * 64;
    int t = threadIdx.x;
    int nodeBase = blockIdx.x * 32;
    int o = t & 127;
    int grp = t >> 7;               // 0 / 1 (16 nodes each)
    int b = o >> 5, d = o & 31;

    unsigned long long acc2[16];
#pragma unroll
    for (int q = 0; q < 16; q++) acc2[q] = 0ull;

    for (int r = 0; r < RR; r++) {
        __syncthreads();
        // stage: fp16 -> fp32 smem (32 nodes x 64 half2 = 2048 per block per r)
#pragma unroll
        for (int q = 0; q < 8; q++) {
            int lin = t + q * 256;              // 0..2047
            int nl = lin >> 6, c2 = lin & 63;
            __half2 hv = Sb[((size_t)r * NN + nodeBase + nl) * 64 + c2];
            float2 f = __half22float2(hv);
            *(float2*)&S[nl][2 * c2] = f;
        }
        __syncthreads();

        unsigned long long wp[16];
#pragma unroll
        for (int c2 = 0; c2 < 16; c2++) {
            const float* wq = W + ((size_t)((r * BB + b) * CC + 2 * c2)) * CC + d;
            wp[c2] = pk2(__ldg(wq), __ldg(wq + CC));
        }

#pragma unroll
        for (int q = 0; q < 16; q++) {
            int nl = grp * 16 + q;
            const unsigned long long* Srow = (const unsigned long long*)&S[nl][b * CC];
#pragma unroll
            for (int c2 = 0; c2 < 16; c2++)
                FMA2(acc2[q], Srow[c2], wp[c2]);
        }
    }

    float* aggj = g_agg + (size_t)j * NN * HH;
#pragma unroll
    for (int q = 0; q < 16; q++) {
        int nl = grp * 16 + q;
        float lo, hi;
        upk2(acc2[q], lo, hi);
        aggj[((size_t)(nodeBase + nl)) * HH + o] = lo + hi;
    }
}

// ============================================================
// root (ALL 3 j in one launch, blockIdx.y = j):
// out[j][row,:] = relu( (row<N ? agg[j] : 0) + h[row,:] @ root[j] + bias[j] )
// IMPORTANT: g_h1 is resolved in DEVICE code (extOut==nullptr selector);
// referencing a __device__ global in host code passes a garbage pointer.
// ============================================================
__global__ __launch_bounds__(512)
void root_fused_kernel(const float* __restrict__ rootL, const float* __restrict__ biasL,
                       int Np, float* __restrict__ extOut, int layer) {
    __shared__ float hT[32][64];    // [k][row]
    __shared__ float rS[32][128];   // [k][col]

    int j = blockIdx.y;
    const float* root = rootL + (size_t)j * HH * HH;
    const float* bias = biasL + (size_t)j * HH;
    const float* hin = layer ? g_h1 : g_h0;
    float* outp = (extOut ? extOut : g_h1) + (size_t)j * (size_t)Np * HH;
    const float* aggj = g_agg + (size_t)j * NN * HH;

    int tx = threadIdx.x;
    int row0 = blockIdx.x * 64;
    int r4 = (tx & 15) * 4;
    int c4 = (tx >> 4) * 4;

    unsigned long long acc2[4][2];
#pragma unroll
    for (int i = 0; i < 4; i++) { acc2[i][0] = 0ull; acc2[i][1] = 0ull; }

    for (int k0 = 0; k0 < HH; k0 += 32) {
        __syncthreads();
        {   // hT: 64 rows x 32 k (transposed store), one float4 per thread
            int row = tx >> 3;
            int kq = (tx & 7) * 4;
            float4 hv = make_float4(0.f, 0.f, 0.f, 0.f);
            int grow = row0 + row;
            if (grow < Np)
                hv = *(const float4*)(hin + (size_t)grow * HH + k0 + kq);
            hT[kq + 0][row] = hv.x;
            hT[kq + 1][row] = hv.y;
            hT[kq + 2][row] = hv.z;
            hT[kq + 3][row] = hv.w;
        }
#pragma unroll
        for (int q = 0; q < 2; q++) {   // rS: 32 k x 128 cols
            int lin = tx + q * 512;
            int k = lin >> 5;
            int cq = (lin & 31) * 4;
            *(float4*)&rS[k][cq] = *(const float4*)(root + (size_t)(k0 + k) * HH + cq);
        }
        __syncthreads();

#pragma unroll
        for (int k = 0; k < 32; k++) {
            float4 a = *(const float4*)&hT[k][r4];
            const unsigned long long* bpp = (const unsigned long long*)&rS[k][c4];
            unsigned long long bp0 = bpp[0];
            unsigned long long bp1 = bpp[1];
            float av[4] = {a.x, a.y, a.z, a.w};
#pragma unroll
            for (int i = 0; i < 4; i++) {
                unsigned long long ai = pk2(av[i], av[i]);
                FMA2(acc2[i][0], ai, bp0);
                FMA2(acc2[i][1], ai, bp1);
            }
        }
    }

    float bv0 = bias[c4 + 0], bv1 = bias[c4 + 1], bv2 = bias[c4 + 2], bv3 = bias[c4 + 3];
#pragma unroll
    for (int i = 0; i < 4; i++) {
        int row = row0 + r4 + i;
        if (row >= Np) break;
        float4 o4;
        upk2(acc2[i][0], o4.x, o4.y);
        upk2(acc2[i][1], o4.z, o4.w);
        o4.x += bv0; o4.y += bv1; o4.z += bv2; o4.w += bv3;
        if (row < NN) {
            const float4 ag = *(const float4*)(aggj + (size_t)row * HH + c4);
            o4.x += ag.x; o4.y += ag.y; o4.z += ag.z; o4.w += ag.w;
        }
        o4.x = fmaxf(o4.x, 0.f);
        o4.y = fmaxf(o4.y, 0.f);
        o4.z = fmaxf(o4.z, 0.f);
        o4.w = fmaxf(o4.w, 0.f);
        *(float4*)(outp + (size_t)row * HH + c4) = o4;
    }
}

// ============================================================
extern "C" void kernel_launch(void* const* d_in, const int* in_sizes, int n_in,
                              void* d_out, int out_size) {
    const float* x  = (const float*)d_in[0];
    const int*   ei = (const int*)  d_in[1];
    const int*   ea = (const int*)  d_in[2];
    const float* fe = (const float*)d_in[3];
    const float* cw = (const float*)d_in[4];
    const float* cr = (const float*)d_in[5];
    const float* cb = (const float*)d_in[6];
    float* out = (float*)d_out;

    const int* src = ei;
    const int* dst = ei + EE;

    gemm_in_kernel<<<NN / 2, 256>>>(x, fe);     // also zeroes g_deg
    k_count<<<(EE + 255) / 256, 256>>>(dst);
    k_prefix<<<1, 1024>>>();
    k_fill<<<(EE + 255) / 256, 256>>>(src, dst, ea);

    for (int layer = 0; layer < 2; layer++) {
        int Np = (layer == 0) ? NN : 3 * NN;

        k_agg<<<NN / 2, 64>>>(layer);           // fused gather+bucket for all 3 j

        const float* Wl    = cw + (size_t)layer * 3 * RR * BB * CC * CC;
        const float* rootL = cr + (size_t)layer * 3 * HH * HH;
        const float* biasL = cb + (size_t)layer * 3 * HH;

        dim3 gT(NN / 32, 3);
        k_transform<<<gT, 256>>>(Wl);           // all 3 j in one launch

        // layer 0 -> device-resolved g_h1 (extOut = nullptr); layer 1 -> d_out
        float* extOut = (layer == 0) ? nullptr : out;
        dim3 gR((Np + 63) / 64, 3);
        root_fused_kernel<<<gR, 512>>>(rootL, biasL, Np, extOut, layer);
    }
}